// round 3
// baseline (speedup 1.0000x reference)
#include <cuda_runtime.h>

#define NB 2048
#define NF 64
#define NR 32
#define NP 16
#define NC 128

// ---------------- scratch (static device allocations are the sanctioned path) ----
__device__ float g_wch [NB*1024];
__device__ float g_vch [NB*1024];
__device__ float g_vep0[NB*1024];
__device__ float g_vep2[NB*1024];
__device__ float g_Wk  [3*NB*1024];

__device__ __forceinline__ float sigmoidf_(float x) { return 1.f/(1.f + __expf(-x)); }

// =====================================================================
// Kernel 1: 7 uniform GEMMs (2048 x 1024 x 128), z selects projection.
//   z=0: wch   z=1: vch   z=2: vep ch0 (col stride 4, off 0)
//   z=3: vep ch2 (stride 4, off 2)     z=4..6: m_W[k]
// =====================================================================
__global__ __launch_bounds__(256) void proj_gemm(
    const float* __restrict__ ctx,
    const float* __restrict__ wch_W, const float* __restrict__ wch_b,
    const float* __restrict__ vch_W, const float* __restrict__ vch_b,
    const float* __restrict__ vep_W, const float* __restrict__ vep_b,
    const float* __restrict__ m_W,   const float* __restrict__ m_Wb)
{
    const float* W; const float* bias; float* outp;
    int nstride = 1, noff = 0, ldw = 1024;
    switch (blockIdx.z) {
        case 0: W = wch_W; bias = wch_b; outp = g_wch; break;
        case 1: W = vch_W; bias = vch_b; outp = g_vch; break;
        case 2: W = vep_W; bias = vep_b; outp = g_vep0; ldw = 4096; nstride = 4; noff = 0; break;
        case 3: W = vep_W; bias = vep_b; outp = g_vep2; ldw = 4096; nstride = 4; noff = 2; break;
        default: { int k = blockIdx.z - 4;
                   W = m_W + k*NC*1024; bias = m_Wb + k*1024; outp = g_Wk + k*NB*1024; } break;
    }
    const int n0 = blockIdx.x * 64;
    const int m0 = blockIdx.y * 64;

    __shared__ float As[64][65];                 // [k][m], pad 65 -> conflict-free
    __shared__ __align__(16) float Bs[64][64];   // [k][n]

    const int t  = threadIdx.x;
    const int tx = t & 15, ty = t >> 4;

    float acc[4][4];
    #pragma unroll
    for (int i = 0; i < 4; i++)
        #pragma unroll
        for (int j = 0; j < 4; j++) acc[i][j] = 0.f;

    for (int k0 = 0; k0 < 128; k0 += 64) {
        #pragma unroll 4
        for (int i = t; i < 64*64; i += 256) {
            int m = i >> 6, k = i & 63;
            As[k][m] = ctx[(m0+m)*NC + k0 + k];
        }
        #pragma unroll 4
        for (int i = t; i < 64*64; i += 256) {
            int k = i >> 6, n = i & 63;
            Bs[k][n] = W[(k0+k)*ldw + (n0+n)*nstride + noff];
        }
        __syncthreads();
        #pragma unroll 16
        for (int k = 0; k < 64; k++) {
            float a0 = As[k][ty*4+0], a1 = As[k][ty*4+1];
            float a2 = As[k][ty*4+2], a3 = As[k][ty*4+3];
            float4 bv = *(const float4*)&Bs[k][tx*4];
            acc[0][0] += a0*bv.x; acc[0][1] += a0*bv.y; acc[0][2] += a0*bv.z; acc[0][3] += a0*bv.w;
            acc[1][0] += a1*bv.x; acc[1][1] += a1*bv.y; acc[1][2] += a1*bv.z; acc[1][3] += a1*bv.w;
            acc[2][0] += a2*bv.x; acc[2][1] += a2*bv.y; acc[2][2] += a2*bv.z; acc[2][3] += a2*bv.w;
            acc[3][0] += a3*bv.x; acc[3][1] += a3*bv.y; acc[3][2] += a3*bv.z; acc[3][3] += a3*bv.w;
        }
        __syncthreads();
    }

    float b0 = bias[(n0+tx*4+0)*nstride + noff];
    float b1 = bias[(n0+tx*4+1)*nstride + noff];
    float b2 = bias[(n0+tx*4+2)*nstride + noff];
    float b3 = bias[(n0+tx*4+3)*nstride + noff];
    #pragma unroll
    for (int i = 0; i < 4; i++) {
        int m = m0 + ty*4 + i;
        float4 o;
        o.x = acc[i][0] + b0; o.y = acc[i][1] + b1;
        o.z = acc[i][2] + b2; o.w = acc[i][3] + b3;
        *(float4*)&outp[m*1024 + n0 + tx*4] = o;
    }
}

// =====================================================================
// Kernel 2: per-batch fused kernel — small projections, mod-softmax,
// match = prod_k sigmoid(score_k), then the 32-step scan with out[F][R]
// held in registers (8 per thread; f = j*8 + warp, r = lane).
// =====================================================================
__global__ __launch_bounds__(256) void scan_kernel(
    const float* __restrict__ form, const float* __restrict__ ctx,
    const float* __restrict__ mod_W, const float* __restrict__ mod_b,
    const float* __restrict__ wdl_W, const float* __restrict__ wdl_b,
    const float* __restrict__ wep_W, const float* __restrict__ wep_b,
    const float* __restrict__ wnc_W, const float* __restrict__ wnc_b,
    const float* __restrict__ wnd_W, const float* __restrict__ wnd_b,
    const float* __restrict__ wne_W, const float* __restrict__ wne_b,
    const float* __restrict__ mb_W,  const float* __restrict__ mb_b,
    float* __restrict__ out)
{
    const int b = blockIdx.x;
    const int t = threadIdx.x;
    const int w = t >> 5, lane = t & 31;

    __shared__ float ctx_s[128];
    __shared__ float form_s[64][33];     // padded: broadcast-free [f][i] reads
    __shared__ float match_s[32][16];    // [r][p]
    __shared__ float big[4096];          // phase1: Wk[3][16][64]; later: wchng|vch|vep0|vep2
    __shared__ float modbuf[96];
    __shared__ float wdlin[16], weplin0[16], weplin2[16];
    __shared__ float mod0_s[16], wdl_s[16], wep0_s[16], wep2_s[16];
    __shared__ float wnc_s[64];
    __shared__ float bk_s[3][16];
    __shared__ float val_s[64];
    __shared__ float attn_s[32];
    __shared__ float scal[4];            // 0:posn 1:gate 2:w_nodeln 3:w_noepen

    if (t < 128) ctx_s[t] = ctx[b*128 + t];
    for (int i = t; i < 2048; i += 256) form_s[i >> 5][i & 31] = form[b*2048 + i];
    __syncthreads();

    // ---- 258 small length-128 projections ----
    for (int j = t; j < 258; j += 256) {
        const float* wp; int stride; float bias; float* dst; int do_exp = 0;
        if (j < 96)        { wp = mod_W + j;                 stride = 96; bias = mod_b[j];        dst = &modbuf[j]; }
        else if (j < 112)  { int p = j-96;  wp = wdl_W + p;  stride = 16; bias = wdl_b[p];        dst = &wdlin[p]; }
        else if (j < 128)  { int p = j-112; wp = wep_W + p*4;   stride = 64; bias = wep_b[p*4];   dst = &weplin0[p]; }
        else if (j < 144)  { int p = j-128; wp = wep_W + p*4+2; stride = 64; bias = wep_b[p*4+2]; dst = &weplin2[p]; }
        else if (j < 208)  { int f = j-144; wp = wnc_W + f;  stride = 64; bias = wnc_b[f];        dst = &wnc_s[f]; do_exp = 1; }
        else if (j < 256)  { int idx = j-208; int k = idx >> 4, p = idx & 15;
                             wp = mb_W + k*128*16 + p; stride = 16; bias = mb_b[k*16+p]; dst = &bk_s[k][p]; }
        else if (j == 256) { wp = wnd_W; stride = 1; bias = wnd_b[0]; dst = &scal[2]; do_exp = 1; }
        else               { wp = wne_W; stride = 1; bias = wne_b[0]; dst = &scal[3]; do_exp = 1; }
        float s = bias;
        #pragma unroll 8
        for (int c = 0; c < 128; c++) s += ctx_s[c]*wp[c*stride];
        *dst = do_exp ? __expf(s) : s;
    }
    // ---- stage Wk[3][P][F] into big ----
    for (int i = t; i < 3072; i += 256)
        big[i] = g_Wk[(i >> 10)*(NB*1024) + b*1024 + (i & 1023)];
    __syncthreads();

    // ---- mod softmax; fold channels into the per-p gate weights ----
    if (t < 16) {
        float m[6], mx = -1e30f;
        #pragma unroll
        for (int ch = 0; ch < 6; ch++) { m[ch] = modbuf[t*6+ch]; mx = fmaxf(mx, m[ch]); }
        float s = 0.f;
        #pragma unroll
        for (int ch = 0; ch < 6; ch++) { m[ch] = __expf(m[ch]-mx); s += m[ch]; }
        float inv = 1.f/s;
        mod0_s[t] = m[0]*inv;               // scales w_chng rows
        wdl_s[t]  = m[1]*inv*wdlin[t];
        wep0_s[t] = m[2]*inv*weplin0[t];    // epen channel 0 uses mod ch 2
        wep2_s[t] = m[4]*inv*weplin2[t];    // epen channel 2 uses mod ch 4
    }
    if (t == 128) scal[0] = 0.f;            // posn = 0

    // ---- match[r][p] = prod_k sigmoid(bk + Wk . forms3)  (== exp(sum logsig)) ----
    for (int pr = t; pr < 512; pr += 256) {
        int p = pr >> 5, r = pr & 31;
        float prod = 1.f;
        #pragma unroll
        for (int k = 0; k < 3; k++) {
            float sc = bk_s[k][p];
            int rr = r + k - 1;                      // prev/self/next shift along R
            if (rr >= 0 && rr < 32) {
                const float* wkp = &big[k*1024 + p*64];
                #pragma unroll 8
                for (int f = 0; f < 64; f++) sc += wkp[f]*form_s[f][rr];
            }
            prod *= sigmoidf_(sc);
        }
        match_s[r][p] = prod;
    }
    __syncthreads();

    // ---- overwrite big with the scan tables ----
    {
        const float* pwch = g_wch  + b*1024;
        const float* pvch = g_vch  + b*1024;
        const float* pv0  = g_vep0 + b*1024;
        const float* pv2  = g_vep2 + b*1024;
        for (int i = t; i < 1024; i += 256) {
            big[i]        = mod0_s[i >> 6]*pwch[i];  // w_chng (mod folded)
            big[1024 + i] = pvch[i];                 // v_chng
            big[2048 + i] = pv0[i];                  // v_epen ch0
            big[3072 + i] = pv2[i];                  // v_epen ch2
        }
    }
    __syncthreads();

    float o[8];
    #pragma unroll
    for (int j = 0; j < 8; j++) o[j] = 0.f;

    // attn = softmax_r( -TAU*(posn-r)^2 ), computed by warp 2 (lane == r)
    auto do_attn = [&]() {
        int r = t - 64;
        float d = scal[0] - (float)r;
        float arg = -2.0f*d*d;
        float mx = arg;
        #pragma unroll
        for (int off = 16; off; off >>= 1) mx = fmaxf(mx, __shfl_xor_sync(0xffffffffu, mx, off));
        float e = __expf(arg - mx);
        float ssum = e;
        #pragma unroll
        for (int off = 16; off; off >>= 1) ssum += __shfl_xor_sync(0xffffffffu, ssum, off);
        attn_s[r] = e / ssum;
    };
    // out = out*(1 - g*a) + g*a*val ;  posn += g
    auto do_bind = [&]() {
        float gg = scal[1];
        float cc = gg * attn_s[lane];
        #pragma unroll
        for (int j = 0; j < 8; j++) {
            float v = val_s[j*8 + w];
            o[j] += cc * (v - o[j]);
        }
        if (t == 0) scal[0] += gg;
    };
    auto epen_phase = [&](int i, const float* wep, const float* vep) {
        if (t < 64) {
            float acc = 0.f;
            #pragma unroll
            for (int p = 0; p < 16; p++) {
                float we = match_s[i][p]*wep[p];
                acc += fmaxf(we, 0.f)*vep[p*64 + t];
            }
            val_s[t] = acc;
        } else if (t < 96) {
            do_attn();
        } else if (t == 96) {
            float s = 0.f;
            #pragma unroll
            for (int p = 0; p < 16; p++) s += match_s[i][p]*wep[p];
            scal[1] = sigmoidf_(s - scal[3]);        // p_epen (gate == posn delta)
        }
    };
    auto chng_phase = [&](int i) {
        if (t < 64) {
            float s1 = 0.f, s2 = 0.f;
            #pragma unroll
            for (int p = 0; p < 16; p++) {
                float wc = match_s[i][p]*big[p*64 + t];
                s1 += wc;
                s2 += fmaxf(wc, 0.f)*big[1024 + p*64 + t];
            }
            float pch  = sigmoidf_(s1 - wnc_s[t]);
            float symi = form_s[t][i];
            val_s[t] = symi + pch*(s2 - symi);       // sym
        } else if (t < 96) {
            do_attn();
        } else if (t == 96) {
            float s = 0.f;
            #pragma unroll
            for (int p = 0; p < 16; p++) s += match_s[i][p]*wdl_s[p];
            scal[1] = 1.f - sigmoidf_(s - scal[2]);  // gate = 1 - p_deln (== posn delta)
        }
    };

    for (int i = 0; i < 32; i++) {
        epen_phase(i, wep0_s, &big[2048]); __syncthreads();
        do_bind();                         __syncthreads();
        chng_phase(i);                     __syncthreads();
        do_bind();                         __syncthreads();
        epen_phase(i, wep2_s, &big[3072]); __syncthreads();
        do_bind();                         __syncthreads();
    }

    #pragma unroll
    for (int j = 0; j < 8; j++)
        out[b*2048 + (j*8 + w)*32 + lane] = o[j];
}

// =====================================================================
extern "C" void kernel_launch(void* const* d_in, const int* in_sizes, int n_in,
                              void* d_out, int out_size)
{
    (void)in_sizes; (void)n_in; (void)out_size;
    const float* form  = (const float*)d_in[0];
    const float* ctx   = (const float*)d_in[1];
    const float* mod_W = (const float*)d_in[2];
    const float* mod_b = (const float*)d_in[3];
    const float* wch_W = (const float*)d_in[4];
    const float* wch_b = (const float*)d_in[5];
    const float* wdl_W = (const float*)d_in[6];
    const float* wdl_b = (const float*)d_in[7];
    const float* wep_W = (const float*)d_in[8];
    const float* wep_b = (const float*)d_in[9];
    const float* vch_W = (const float*)d_in[10];
    const float* vch_b = (const float*)d_in[11];
    const float* vep_W = (const float*)d_in[12];
    const float* vep_b = (const float*)d_in[13];
    const float* wnc_W = (const float*)d_in[14];
    const float* wnc_b = (const float*)d_in[15];
    const float* wnd_W = (const float*)d_in[16];
    const float* wnd_b = (const float*)d_in[17];
    const float* wne_W = (const float*)d_in[18];
    const float* wne_b = (const float*)d_in[19];
    const float* m_W   = (const float*)d_in[20];
    const float* m_Wb  = (const float*)d_in[21];
    const float* mb_W  = (const float*)d_in[22];
    const float* mb_b  = (const float*)d_in[23];

    dim3 ggrid(1024/64, NB/64, 7);
    proj_gemm<<<ggrid, 256>>>(ctx, wch_W, wch_b, vch_W, vch_b, vep_W, vep_b, m_W, m_Wb);

    scan_kernel<<<NB, 256>>>(form, ctx,
                             mod_W, mod_b, wdl_W, wdl_b, wep_W, wep_b,
                             wnc_W, wnc_b, wnd_W, wnd_b, wne_W, wne_b,
                             mb_W, mb_b, (float*)d_out);
}

// round 4
// speedup vs baseline: 1.1584x; 1.1584x over previous
#include <cuda_runtime.h>

#define NB 2048
#define NF 64
#define NR 32
#define NP 16
#define NC 128

// ---------------- scratch ----------------
__device__ float g_wch [NB*1024];
__device__ float g_vch [NB*1024];
__device__ float g_vep0[NB*1024];
__device__ float g_vep2[NB*1024];
__device__ float g_Wk  [3*NB*1024];

__device__ __forceinline__ float sigmoidf_(float x) { return 1.f/(1.f + __expf(-x)); }

// =====================================================================
// Kernel 1: 7 uniform GEMMs (2048 x 1024 x 128), z selects projection.
// =====================================================================
__global__ __launch_bounds__(256) void proj_gemm(
    const float* __restrict__ ctx,
    const float* __restrict__ wch_W, const float* __restrict__ wch_b,
    const float* __restrict__ vch_W, const float* __restrict__ vch_b,
    const float* __restrict__ vep_W, const float* __restrict__ vep_b,
    const float* __restrict__ m_W,   const float* __restrict__ m_Wb)
{
    const float* W; const float* bias; float* outp;
    int nstride = 1, noff = 0, ldw = 1024;
    switch (blockIdx.z) {
        case 0: W = wch_W; bias = wch_b; outp = g_wch; break;
        case 1: W = vch_W; bias = vch_b; outp = g_vch; break;
        case 2: W = vep_W; bias = vep_b; outp = g_vep0; ldw = 4096; nstride = 4; noff = 0; break;
        case 3: W = vep_W; bias = vep_b; outp = g_vep2; ldw = 4096; nstride = 4; noff = 2; break;
        default: { int k = blockIdx.z - 4;
                   W = m_W + k*NC*1024; bias = m_Wb + k*1024; outp = g_Wk + k*NB*1024; } break;
    }
    const int n0 = blockIdx.x * 64;
    const int m0 = blockIdx.y * 64;

    __shared__ float As[64][65];
    __shared__ __align__(16) float Bs[64][64];

    const int t  = threadIdx.x;
    const int tx = t & 15, ty = t >> 4;

    float acc[4][4];
    #pragma unroll
    for (int i = 0; i < 4; i++)
        #pragma unroll
        for (int j = 0; j < 4; j++) acc[i][j] = 0.f;

    for (int k0 = 0; k0 < 128; k0 += 64) {
        #pragma unroll 4
        for (int i = t; i < 64*64; i += 256) {
            int m = i >> 6, k = i & 63;
            As[k][m] = ctx[(m0+m)*NC + k0 + k];
        }
        #pragma unroll 4
        for (int i = t; i < 64*64; i += 256) {
            int k = i >> 6, n = i & 63;
            Bs[k][n] = W[(k0+k)*ldw + (n0+n)*nstride + noff];
        }
        __syncthreads();
        #pragma unroll 16
        for (int k = 0; k < 64; k++) {
            float a0 = As[k][ty*4+0], a1 = As[k][ty*4+1];
            float a2 = As[k][ty*4+2], a3 = As[k][ty*4+3];
            float4 bv = *(const float4*)&Bs[k][tx*4];
            acc[0][0] += a0*bv.x; acc[0][1] += a0*bv.y; acc[0][2] += a0*bv.z; acc[0][3] += a0*bv.w;
            acc[1][0] += a1*bv.x; acc[1][1] += a1*bv.y; acc[1][2] += a1*bv.z; acc[1][3] += a1*bv.w;
            acc[2][0] += a2*bv.x; acc[2][1] += a2*bv.y; acc[2][2] += a2*bv.z; acc[2][3] += a2*bv.w;
            acc[3][0] += a3*bv.x; acc[3][1] += a3*bv.y; acc[3][2] += a3*bv.z; acc[3][3] += a3*bv.w;
        }
        __syncthreads();
    }

    float b0 = bias[(n0+tx*4+0)*nstride + noff];
    float b1 = bias[(n0+tx*4+1)*nstride + noff];
    float b2 = bias[(n0+tx*4+2)*nstride + noff];
    float b3 = bias[(n0+tx*4+3)*nstride + noff];
    #pragma unroll
    for (int i = 0; i < 4; i++) {
        int m = m0 + ty*4 + i;
        float4 o;
        o.x = acc[i][0] + b0; o.y = acc[i][1] + b1;
        o.z = acc[i][2] + b2; o.w = acc[i][3] + b3;
        *(float4*)&outp[m*1024 + n0 + tx*4] = o;
    }
}

// =====================================================================
// Kernel 2: per-batch — the "scan" is linear in out, so it factorizes:
//   out[f][r] = sum_t val_t[f] * w_t[r],
//   w_t[r] = c_t[r] * prod_{s>t}(1 - c_s[r]),
//   c_t[r] = g_t * softmax_r(-2 (posn_t - r)^2),   posn_t = excl-prefix(g).
// All of g, val, match are state-independent -> fully parallel.
// =====================================================================
__global__ __launch_bounds__(256) void scan_kernel(
    const float* __restrict__ form, const float* __restrict__ ctx,
    const float* __restrict__ mod_W, const float* __restrict__ mod_b,
    const float* __restrict__ wdl_W, const float* __restrict__ wdl_b,
    const float* __restrict__ wep_W, const float* __restrict__ wep_b,
    const float* __restrict__ wnc_W, const float* __restrict__ wnc_b,
    const float* __restrict__ wnd_W, const float* __restrict__ wnd_b,
    const float* __restrict__ wne_W, const float* __restrict__ wne_b,
    const float* __restrict__ mb_W,  const float* __restrict__ mb_b,
    float* __restrict__ out)
{
    const int b    = blockIdx.x;
    const int tid  = threadIdx.x;
    const int lane = tid & 31, wid = tid >> 5;

    __shared__ float ctx_s[128];
    __shared__ float form_s[64][32];                  // [f][r]
    __shared__ __align__(16) float big[4096];         // Wk[3][16][64] -> wch|vch|vep0|vep2
    __shared__ float match_s[32][16];                 // [r][p]
    __shared__ float modbuf[96];
    __shared__ float wdlin[16], weplin0[16], weplin2[16];
    __shared__ float mod0_s[16], wdl_s[16], wep0_s[16], wep2_s[16];
    __shared__ float wnc_s[64];
    __shared__ float bk_s[3][16];
    __shared__ float g_s[96], posn_s[96];
    __shared__ float cw_s[96*32];                     // c, then w in place
    __shared__ float segp_s[8*32];                    // per-segment suffix (1-c) products
    __shared__ __align__(16) float val_s[16][64];     // val tile
    __shared__ float scal2[2];                        // [0]=exp(wnd) [1]=exp(wne)

    if (tid < 128) ctx_s[tid] = ctx[b*128 + tid];
    for (int i = tid; i < 2048; i += 256) form_s[i >> 5][i & 31] = form[b*2048 + i];
    __syncthreads();

    // ---- 258 small length-128 projections + stage Wk ----
    for (int j = tid; j < 258; j += 256) {
        const float* wp; int stride; float bias; float* dst; int do_exp = 0;
        if (j < 96)        { wp = mod_W + j;                 stride = 96; bias = mod_b[j];        dst = &modbuf[j]; }
        else if (j < 112)  { int p = j-96;  wp = wdl_W + p;  stride = 16; bias = wdl_b[p];        dst = &wdlin[p]; }
        else if (j < 128)  { int p = j-112; wp = wep_W + p*4;   stride = 64; bias = wep_b[p*4];   dst = &weplin0[p]; }
        else if (j < 144)  { int p = j-128; wp = wep_W + p*4+2; stride = 64; bias = wep_b[p*4+2]; dst = &weplin2[p]; }
        else if (j < 208)  { int f = j-144; wp = wnc_W + f;  stride = 64; bias = wnc_b[f];        dst = &wnc_s[f]; do_exp = 1; }
        else if (j < 256)  { int idx = j-208; int k = idx >> 4, p = idx & 15;
                             wp = mb_W + k*128*16 + p; stride = 16; bias = mb_b[k*16+p]; dst = &bk_s[k][p]; }
        else if (j == 256) { wp = wnd_W; stride = 1; bias = wnd_b[0]; dst = &scal2[0]; do_exp = 1; }
        else               { wp = wne_W; stride = 1; bias = wne_b[0]; dst = &scal2[1]; do_exp = 1; }
        float s = bias;
        #pragma unroll 8
        for (int c = 0; c < 128; c++) s += ctx_s[c]*wp[c*stride];
        *dst = do_exp ? __expf(s) : s;
    }
    for (int i = tid; i < 3072; i += 256)
        big[i] = g_Wk[(i >> 10)*(NB*1024) + b*1024 + (i & 1023)];
    __syncthreads();

    // ---- mod softmax fold (t<16) + match (all threads) ----
    if (tid < 16) {
        float m[6], mx = -1e30f;
        #pragma unroll
        for (int ch = 0; ch < 6; ch++) { m[ch] = modbuf[tid*6+ch]; mx = fmaxf(mx, m[ch]); }
        float s = 0.f;
        #pragma unroll
        for (int ch = 0; ch < 6; ch++) { m[ch] = __expf(m[ch]-mx); s += m[ch]; }
        float inv = 1.f/s;
        mod0_s[tid] = m[0]*inv;
        wdl_s[tid]  = m[1]*inv*wdlin[tid];
        wep0_s[tid] = m[2]*inv*weplin0[tid];
        wep2_s[tid] = m[4]*inv*weplin2[tid];
    }
    for (int pr = tid; pr < 512; pr += 256) {
        int p = pr >> 5, r = pr & 31;
        float prod = 1.f;
        #pragma unroll
        for (int k = 0; k < 3; k++) {
            float sc = bk_s[k][p];
            int rr = r + k - 1;
            if (rr >= 0 && rr < 32) {
                const float* wkp = &big[k*1024 + p*64];
                #pragma unroll
                for (int f = 0; f < 64; f += 4) {
                    float4 w4 = *(const float4*)&wkp[f];
                    sc += w4.x*form_s[f  ][rr] + w4.y*form_s[f+1][rr]
                        + w4.z*form_s[f+2][rr] + w4.w*form_s[f+3][rr];
                }
            }
            prod *= sigmoidf_(sc);
        }
        match_s[r][p] = prod;
    }
    __syncthreads();

    // ---- stage value tables (overwrite Wk) + all 96 gates ----
    {
        const float* pwch = g_wch  + b*1024;
        const float* pvch = g_vch  + b*1024;
        const float* pv0  = g_vep0 + b*1024;
        const float* pv2  = g_vep2 + b*1024;
        for (int i = tid; i < 1024; i += 256) {
            big[i]        = mod0_s[i >> 6]*pwch[i];
            big[1024 + i] = pvch[i];
            big[2048 + i] = pv0[i];
            big[3072 + i] = pv2[i];
        }
    }
    if (tid < 96) {
        int i = tid/3, ph = tid - 3*i;
        const float* wv = (ph == 0) ? wep0_s : (ph == 1 ? wdl_s : wep2_s);
        float s = 0.f;
        #pragma unroll
        for (int p = 0; p < 16; p++) s += match_s[i][p]*wv[p];
        float gg = (ph == 1) ? (1.f - sigmoidf_(s - scal2[0]))
                             : sigmoidf_(s - scal2[1]);
        g_s[tid] = gg;
    }
    __syncthreads();

    // ---- exclusive prefix of gates -> posn (warp 0) ----
    if (wid == 0) {
        float a0 = g_s[lane*3+0], a1 = g_s[lane*3+1], a2 = g_s[lane*3+2];
        float loc = a0 + a1 + a2;
        float sc = loc;
        #pragma unroll
        for (int off = 1; off < 32; off <<= 1) {
            float v = __shfl_up_sync(0xffffffffu, sc, off);
            if (lane >= off) sc += v;
        }
        float excl = sc - loc;
        posn_s[lane*3+0] = excl;
        posn_s[lane*3+1] = excl + a0;
        posn_s[lane*3+2] = excl + a0 + a1;
    }
    __syncthreads();

    // ---- c_t[r] = g_t * softmax_r(-2(posn_t - r)^2); warp handles 12 t's ----
    #pragma unroll
    for (int k2 = 0; k2 < 12; k2++) {
        int st = wid*12 + k2;
        float pp = posn_s[st];
        float d  = pp - (float)lane;
        float rstar = fminf(fmaxf(rintf(pp), 0.f), 31.f);
        float dm = pp - rstar;
        float mx = -2.f*dm*dm;
        float e  = __expf(-2.f*d*d - mx);
        float ssum = e;
        #pragma unroll
        for (int off = 16; off; off >>= 1) ssum += __shfl_xor_sync(0xffffffffu, ssum, off);
        cw_s[st*32 + lane] = g_s[st]*e/ssum;
    }
    __syncthreads();

    // ---- suffix products: w_t = c_t * prod_{s>t}(1-c_s), segmented 2-pass ----
    {
        int st0 = wid*12;
        float run = 1.f;
        #pragma unroll
        for (int k2 = 11; k2 >= 0; k2--) {
            float cc = cw_s[(st0+k2)*32 + lane];
            cw_s[(st0+k2)*32 + lane] = cc*run;
            run *= (1.f - cc);
        }
        segp_s[wid*32 + lane] = run;
    }
    __syncthreads();
    {
        float mult = 1.f;
        #pragma unroll
        for (int w2 = 7; w2 >= 1; w2--) {
            float sp = segp_s[w2*32 + lane];
            if (w2 > wid) mult *= sp;
        }
        if (mult != 1.f) {
            int st0 = wid*12;
            #pragma unroll
            for (int k2 = 0; k2 < 12; k2++)
                cw_s[(st0+k2)*32 + lane] *= mult;
        }
    }
    __syncthreads();

    // ---- tiles: compute val[16][64], then accumulate out += w*val ----
    float o[8];
    #pragma unroll
    for (int j = 0; j < 8; j++) o[j] = 0.f;

    const int fb = wid*8;

    for (int tile = 0; tile < 6; tile++) {
        const int t0 = tile*16;
        {
            int tt = tid >> 4, f4 = tid & 15;
            int st = t0 + tt;
            int i = st/3, ph = st - 3*i;
            float4 v;
            if (ph == 1) {
                float4 s1 = {0,0,0,0}, s2 = {0,0,0,0};
                #pragma unroll
                for (int p = 0; p < 16; p++) {
                    float m = match_s[i][p];
                    float4 wc4 = *(const float4*)&big[p*64 + f4*4];
                    float4 vc4 = *(const float4*)&big[1024 + p*64 + f4*4];
                    float w0 = m*wc4.x, w1 = m*wc4.y, w2 = m*wc4.z, w3 = m*wc4.w;
                    s1.x += w0; s1.y += w1; s1.z += w2; s1.w += w3;
                    s2.x += fmaxf(w0,0.f)*vc4.x; s2.y += fmaxf(w1,0.f)*vc4.y;
                    s2.z += fmaxf(w2,0.f)*vc4.z; s2.w += fmaxf(w3,0.f)*vc4.w;
                }
                int f = f4*4;
                float sy0 = form_s[f  ][i], sy1 = form_s[f+1][i];
                float sy2 = form_s[f+2][i], sy3 = form_s[f+3][i];
                float p0 = sigmoidf_(s1.x - wnc_s[f  ]);
                float p1 = sigmoidf_(s1.y - wnc_s[f+1]);
                float p2 = sigmoidf_(s1.z - wnc_s[f+2]);
                float p3 = sigmoidf_(s1.w - wnc_s[f+3]);
                v.x = sy0 + p0*(s2.x - sy0);
                v.y = sy1 + p1*(s2.y - sy1);
                v.z = sy2 + p2*(s2.z - sy2);
                v.w = sy3 + p3*(s2.w - sy3);
            } else {
                const float* vp = &big[(ph == 0) ? 2048 : 3072];
                const float* wv = (ph == 0) ? wep0_s : wep2_s;
                float4 s = {0,0,0,0};
                #pragma unroll
                for (int p = 0; p < 16; p++) {
                    float we = fmaxf(match_s[i][p]*wv[p], 0.f);
                    float4 v4 = *(const float4*)&vp[p*64 + f4*4];
                    s.x += we*v4.x; s.y += we*v4.y; s.z += we*v4.z; s.w += we*v4.w;
                }
                v = s;
            }
            *(float4*)&val_s[tt][f4*4] = v;
        }
        __syncthreads();
        #pragma unroll
        for (int tt = 0; tt < 16; tt++) {
            float ww = cw_s[(t0+tt)*32 + lane];
            float4 v0 = *(const float4*)&val_s[tt][fb];
            float4 v1 = *(const float4*)&val_s[tt][fb+4];
            o[0] += ww*v0.x; o[1] += ww*v0.y; o[2] += ww*v0.z; o[3] += ww*v0.w;
            o[4] += ww*v1.x; o[5] += ww*v1.y; o[6] += ww*v1.z; o[7] += ww*v1.w;
        }
        __syncthreads();
    }

    #pragma unroll
    for (int j = 0; j < 8; j++)
        out[b*2048 + (fb + j)*32 + lane] = o[j];
}

// =====================================================================
extern "C" void kernel_launch(void* const* d_in, const int* in_sizes, int n_in,
                              void* d_out, int out_size)
{
    (void)in_sizes; (void)n_in; (void)out_size;
    const float* form  = (const float*)d_in[0];
    const float* ctx   = (const float*)d_in[1];
    const float* mod_W = (const float*)d_in[2];
    const float* mod_b = (const float*)d_in[3];
    const float* wch_W = (const float*)d_in[4];
    const float* wch_b = (const float*)d_in[5];
    const float* wdl_W = (const float*)d_in[6];
    const float* wdl_b = (const float*)d_in[7];
    const float* wep_W = (const float*)d_in[8];
    const float* wep_b = (const float*)d_in[9];
    const float* vch_W = (const float*)d_in[10];
    const float* vch_b = (const float*)d_in[11];
    const float* vep_W = (const float*)d_in[12];
    const float* vep_b = (const float*)d_in[13];
    const float* wnc_W = (const float*)d_in[14];
    const float* wnc_b = (const float*)d_in[15];
    const float* wnd_W = (const float*)d_in[16];
    const float* wnd_b = (const float*)d_in[17];
    const float* wne_W = (const float*)d_in[18];
    const float* wne_b = (const float*)d_in[19];
    const float* m_W   = (const float*)d_in[20];
    const float* m_Wb  = (const float*)d_in[21];
    const float* mb_W  = (const float*)d_in[22];
    const float* mb_b  = (const float*)d_in[23];

    dim3 ggrid(1024/64, NB/64, 7);
    proj_gemm<<<ggrid, 256>>>(ctx, wch_W, wch_b, vch_W, vch_b, vep_W, vep_b, m_W, m_Wb);

    scan_kernel<<<NB, 256>>>(form, ctx,
                             mod_W, mod_b, wdl_W, wdl_b, wep_W, wep_b,
                             wnc_W, wnc_b, wnd_W, wnd_b, wne_W, wne_b,
                             mb_W, mb_b, (float*)d_out);
}